// round 13
// baseline (speedup 1.0000x reference)
#include <cuda_runtime.h>
#include <cstdint>

// out[i] = sum_k targets[i,k] * temporal_bases[batch_indices[1], k] * scaling[k]
// B=8192, K=1024, T=16384. HBM-streaming GEMV (32 MB of targets, read once).
// Dedicated-producer TMA pipeline: 1 producer warp issues 4 KB row chunks into
// a 16-stage smem ring; 8 consumer warps each dot one row per chunk.

static constexpr int K = 1024;
static constexpr int CONSUMERS = 8;                  // consumer warps
static constexpr int THREADS = (CONSUMERS + 1) * 32; // 288: 8 consumers + 1 producer
static constexpr int F4 = K / 4 / 32;                // 8 float4 per lane per row
static constexpr unsigned CHUNK_BYTES = K * 4;       // 4096: one row
static constexpr int STAGES = 16;                    // 64 KB ring
static constexpr int NUM_SMS = 148;
static constexpr int GRID = NUM_SMS * 2;             // 296 CTAs, single wave

static constexpr int OFF_FULL  = 0;                  // 16 x u64
static constexpr int OFF_EMPTY = 128;                // 16 x u64
static constexpr int OFF_RING  = 512;                // 16 x 4 KB
static constexpr int SMEM_SIZE = OFF_RING + STAGES * (int)CHUNK_BYTES;  // 66048

__device__ __forceinline__ uint32_t smem_u32(const void* p) {
    return (uint32_t)__cvta_generic_to_shared(p);
}
__device__ __forceinline__ void mbar_init(uint32_t a, uint32_t cnt) {
    asm volatile("mbarrier.init.shared.b64 [%0], %1;" :: "r"(a), "r"(cnt) : "memory");
}
__device__ __forceinline__ void mbar_expect_tx(uint32_t a, uint32_t bytes) {
    asm volatile("mbarrier.arrive.expect_tx.shared.b64 _, [%0], %1;"
                 :: "r"(a), "r"(bytes) : "memory");
}
__device__ __forceinline__ void mbar_arrive(uint32_t a) {
    asm volatile("mbarrier.arrive.shared::cta.b64 _, [%0];"
                 :: "r"(a) : "memory");
}
__device__ __forceinline__ void mbar_wait(uint32_t a, uint32_t parity) {
    asm volatile(
        "{\n\t"
        ".reg .pred P;\n\t"
        "WL_%=:\n\t"
        "mbarrier.try_wait.parity.acquire.cta.shared::cta.b64 P, [%0], %1, 0x989680;\n\t"
        "@P bra WD_%=;\n\t"
        "bra WL_%=;\n\t"
        "WD_%=:\n\t"
        "}"
        :: "r"(a), "r"(parity) : "memory");
}
__device__ __forceinline__ void bulk_g2s(uint32_t dst, const void* src,
                                         uint32_t bytes, uint32_t mbar) {
    asm volatile(
        "cp.async.bulk.shared::cta.global.mbarrier::complete_tx::bytes [%0], [%1], %2, [%3];"
        :: "r"(dst), "l"(src), "r"(bytes), "r"(mbar) : "memory");
}

__global__ __launch_bounds__(THREADS, 2)
void recompose_tma_kernel(const float* __restrict__ targets,
                          const float* __restrict__ bases,
                          const float* __restrict__ scaling,
                          const int* __restrict__ batch_indices,
                          int B, int T,
                          float* __restrict__ out) {
    extern __shared__ char smem[];
    const uint32_t base   = smem_u32(smem);
    const uint32_t full0  = base + OFF_FULL;
    const uint32_t empty0 = base + OFF_EMPTY;

    const int tid  = threadIdx.x;
    const int warp = tid >> 5;
    const int lane = tid & 31;

    if (tid == 0) {
        #pragma unroll
        for (int s = 0; s < STAGES; s++) {
            mbar_init(full0  + 8u * s, 1);   // completes via arrive.expect_tx + tx bytes
            mbar_init(empty0 + 8u * s, 1);   // one lane-0 arrive from the consuming warp
        }
    }
    __syncthreads();   // barriers visible to TMA + all waiters

    // chunk j -> row (blockIdx.x + j*gridDim.x), consumed by warp (j % 8),
    // staged in slot (j % 16).
    const int n_local = (B - blockIdx.x + gridDim.x - 1) / gridDim.x;   // 27 or 28

    if (warp == CONSUMERS) {
        // ---------------- producer warp (lane 0 only) ----------------
        if (lane == 0) {
            for (int j = 0; j < n_local; j++) {
                const int s = j & (STAGES - 1);
                if (j >= STAGES)
                    mbar_wait(empty0 + 8u * s, ((unsigned)(j >> 4) - 1u) & 1u);
                const uint32_t fb = full0 + 8u * s;
                mbar_expect_tx(fb, CHUNK_BYTES);
                bulk_g2s(base + OFF_RING + s * CHUNK_BYTES,
                         targets + (size_t)(blockIdx.x + (size_t)j * gridDim.x) * K,
                         CHUNK_BYTES, fb);
            }
        }
        return;
    }

    // ---------------- consumer warps (0..7) ----------------
    // Load c = bases[t,:]*scaling straight into registers; overlaps with the
    // producer's first TMA chunks already in flight.
    int t = batch_indices[1];
    t = min(max(t, 0), T - 1);
    const float4* __restrict__ b4 = reinterpret_cast<const float4*>(bases + (size_t)t * K);
    const float4* __restrict__ s4 = reinterpret_cast<const float4*>(scaling);

    float4 c[F4];
    #pragma unroll
    for (int q = 0; q < F4; q++) {
        const float4 b = __ldg(b4 + lane + 32 * q);
        const float4 s = __ldg(s4 + lane + 32 * q);
        c[q] = make_float4(b.x * s.x, b.y * s.y, b.z * s.z, b.w * s.w);
    }

    for (int j = warp; j < n_local; j += CONSUMERS) {
        const int s = j & (STAGES - 1);
        const unsigned par = (unsigned)(j >> 4) & 1u;
        const int row = blockIdx.x + j * gridDim.x;

        mbar_wait(full0 + 8u * s, par);

        const float4* __restrict__ a4 =
            reinterpret_cast<const float4*>(smem + OFF_RING + s * CHUNK_BYTES);

        float sum = 0.0f;
        #pragma unroll
        for (int q = 0; q < F4; q++) {
            const float4 a = a4[lane + 32 * q];
            sum += a.x * c[q].x + a.y * c[q].y + a.z * c[q].z + a.w * c[q].w;
        }
        #pragma unroll
        for (int off = 16; off > 0; off >>= 1)
            sum += __shfl_xor_sync(0xffffffffu, sum, off);

        if (lane == 0) {
            out[row] = sum;
            mbar_arrive(empty0 + 8u * s);
        }
    }
}

extern "C" void kernel_launch(void* const* d_in, const int* in_sizes, int n_in,
                              void* d_out, int out_size) {
    const float* targets = nullptr;   // B*K
    const float* bases   = nullptr;   // T*K
    const float* scaling = nullptr;   // K
    const int*   indices = nullptr;   // B
    long targets_n = 0, bases_n = 0;

    for (int j = 0; j < n_in; j++) {
        long n = in_sizes[j];
        if (n == K) {
            scaling = (const float*)d_in[j];
        } else if (n == 8192) {
            indices = (const int*)d_in[j];
        } else if (n == 8192L * K) {
            targets = (const float*)d_in[j];
            targets_n = n;
        } else {
            bases = (const float*)d_in[j];
            bases_n = n;
        }
    }
    if (!targets || !bases || !scaling || !indices) return;

    const int B = (int)(targets_n / K);   // 8192
    const int T = (int)(bases_n / K);     // 16384
    float* out = (float*)d_out;

    static bool attr_set = false;
    if (!attr_set) {
        cudaFuncSetAttribute(recompose_tma_kernel,
                             cudaFuncAttributeMaxDynamicSharedMemorySize, SMEM_SIZE);
        attr_set = true;
    }
    recompose_tma_kernel<<<GRID, THREADS, SMEM_SIZE>>>(targets, bases, scaling,
                                                       indices, B, T, out);
}

// round 14
// speedup vs baseline: 1.1696x; 1.1696x over previous
#include <cuda_runtime.h>
#include <cstdint>

// out[i] = sum_k targets[i,k] * temporal_bases[batch_indices[1], k] * scaling[k]
// B=8192, K=1024, T=16384. HBM/L2-streaming GEMV (32 MB of targets).
// Maximal-parallelism shape: 8192 fully independent warps, one row each.
// No shared memory, no block sync, no pipeline — each warp is one burst of
// ~24 LDG.128 followed by FMAs, a 5-shuffle reduce, and one store.

static constexpr int K = 1024;
static constexpr int THREADS = 128;            // 4 warps per CTA
static constexpr int WARPS = THREADS / 32;
static constexpr int F4 = K / 4 / 32;          // 8 float4 per lane per row

__global__ __launch_bounds__(THREADS)
void recompose_gemv_kernel(const float* __restrict__ targets,
                           const float* __restrict__ bases,
                           const float* __restrict__ scaling,
                           const int* __restrict__ batch_indices,
                           int B, int T,
                           float* __restrict__ out) {
    const int warp = threadIdx.x >> 5;
    const int lane = threadIdx.x & 31;
    const int row  = blockIdx.x * WARPS + warp;
    if (row >= B) return;

    int t = batch_indices[1];
    t = min(max(t, 0), T - 1);

    const float4* __restrict__ a4 = reinterpret_cast<const float4*>(targets + (size_t)row * K);
    const float4* __restrict__ b4 = reinterpret_cast<const float4*>(bases + (size_t)t * K);
    const float4* __restrict__ s4 = reinterpret_cast<const float4*>(scaling);

    // Issue the long-latency row loads first — 8 independent LDG.128.
    float4 a[F4];
    #pragma unroll
    for (int q = 0; q < F4; q++)
        a[q] = a4[lane + 32 * q];

    // bases/scaling are shared by every warp on the chip: L2/L1-hot.
    float4 c[F4];
    #pragma unroll
    for (int q = 0; q < F4; q++) {
        const float4 b = __ldg(b4 + lane + 32 * q);
        const float4 s = __ldg(s4 + lane + 32 * q);
        c[q] = make_float4(b.x * s.x, b.y * s.y, b.z * s.z, b.w * s.w);
    }

    float sum = 0.0f;
    #pragma unroll
    for (int q = 0; q < F4; q++)
        sum += a[q].x * c[q].x + a[q].y * c[q].y + a[q].z * c[q].z + a[q].w * c[q].w;

    #pragma unroll
    for (int off = 16; off > 0; off >>= 1)
        sum += __shfl_xor_sync(0xffffffffu, sum, off);

    if (lane == 0)
        out[row] = sum;
}

extern "C" void kernel_launch(void* const* d_in, const int* in_sizes, int n_in,
                              void* d_out, int out_size) {
    // Resolve inputs by unique element counts, robust to metadata ordering.
    const float* targets = nullptr;   // B*K  = 8388608
    const float* bases   = nullptr;   // T*K  = 16777216
    const float* scaling = nullptr;   // K    = 1024
    const int*   indices = nullptr;   // B    = 8192
    long targets_n = 0, bases_n = 0;

    for (int j = 0; j < n_in; j++) {
        long n = in_sizes[j];
        if (n == K) {
            scaling = (const float*)d_in[j];
        } else if (n == 8192) {
            indices = (const int*)d_in[j];
        } else if (n == 8192L * K) {
            targets = (const float*)d_in[j];
            targets_n = n;
        } else {
            bases = (const float*)d_in[j];
            bases_n = n;
        }
    }
    if (!targets || !bases || !scaling || !indices) return;

    const int B = (int)(targets_n / K);   // 8192
    const int T = (int)(bases_n / K);     // 16384
    float* out = (float*)d_out;

    const int grid = (B + WARPS - 1) / WARPS;   // 2048 CTAs, one row per warp
    recompose_gemv_kernel<<<grid, THREADS>>>(targets, bases, scaling, indices, B, T, out);
}

// round 17
// speedup vs baseline: 1.6949x; 1.4492x over previous
#include <cuda_runtime.h>
#include <cuda_bf16.h>

// out[i] = sum_k targets[i,k] * temporal_bases[batch_indices[1], k] * scaling[k]
// B=8192, K=1024, T=16384. HBM-streaming GEMV (32 MB of targets, read once).
// R5 structure (measured best): warp-per-row, 2-deep register pipeline,
// prefetch-next-before-reduce-current. Only change: grid = 296 = exactly
// 2 CTAs/SM for uniform residency (R5 had 256 -> 40 SMs half-loaded).

static constexpr int K = 1024;
static constexpr int THREADS = 256;            // 8 warps
static constexpr int WARPS = THREADS / 32;
static constexpr int F4 = K / 4 / 32;          // 8 float4 per lane per row
static constexpr int NUM_SMS = 148;
static constexpr int GRID = NUM_SMS * 2;       // 296 CTAs, 2368 warps, one wave

__device__ __forceinline__ void load_row(const float4* __restrict__ a4, float4 (&buf)[F4], int lane) {
    #pragma unroll
    for (int j = 0; j < F4; j++)
        buf[j] = a4[lane + 32 * j];
}

__device__ __forceinline__ float dot_row(const float4 (&a)[F4], const float4 (&c)[F4]) {
    float s = 0.0f;
    #pragma unroll
    for (int j = 0; j < F4; j++)
        s += a[j].x * c[j].x + a[j].y * c[j].y + a[j].z * c[j].z + a[j].w * c[j].w;
    return s;
}

__global__ __launch_bounds__(THREADS, 2)
void recompose_gemv_kernel(const float* __restrict__ targets,
                           const float* __restrict__ bases,
                           const float* __restrict__ scaling,
                           const int* __restrict__ batch_indices,
                           int B, int T,
                           float* __restrict__ out) {
    __shared__ float4 cs[K / 4];               // bases[t,:] * scaling (4 KB)

    int t = batch_indices[1];
    t = min(max(t, 0), T - 1);

    {   // stage combined vector once per CTA
        const float4 b = reinterpret_cast<const float4*>(bases + (size_t)t * K)[threadIdx.x];
        const float4 s = reinterpret_cast<const float4*>(scaling)[threadIdx.x];
        cs[threadIdx.x] = make_float4(b.x * s.x, b.y * s.y, b.z * s.z, b.w * s.w);
    }
    __syncthreads();

    const int warp = threadIdx.x >> 5;
    const int lane = threadIdx.x & 31;
    const int stride = GRID * WARPS;           // 2368

    // per-warp copy of c in registers (conflict-free LDS)
    float4 c[F4];
    #pragma unroll
    for (int j = 0; j < F4; j++)
        c[j] = cs[lane + 32 * j];

    int row = blockIdx.x * WARPS + warp;
    if (row >= B) return;

    float4 A0[F4], A1[F4];
    load_row(reinterpret_cast<const float4*>(targets + (size_t)row * K), A0, lane);

    while (true) {
        // ---- stage: A0 valid for `row`; prefetch row+stride into A1 ----
        int r1 = row + stride;
        if (r1 < B)
            load_row(reinterpret_cast<const float4*>(targets + (size_t)r1 * K), A1, lane);

        {
            float sum = dot_row(A0, c);
            #pragma unroll
            for (int off = 16; off > 0; off >>= 1)
                sum += __shfl_xor_sync(0xffffffffu, sum, off);
            if (lane == 0) out[row] = sum;
        }
        if (r1 >= B) break;

        // ---- stage: A1 valid for r1; prefetch r1+stride into A0 ----
        int r2 = r1 + stride;
        if (r2 < B)
            load_row(reinterpret_cast<const float4*>(targets + (size_t)r2 * K), A0, lane);

        {
            float sum = dot_row(A1, c);
            #pragma unroll
            for (int off = 16; off > 0; off >>= 1)
                sum += __shfl_xor_sync(0xffffffffu, sum, off);
            if (lane == 0) out[r1] = sum;
        }
        if (r2 >= B) break;

        row = r2;
    }
}

extern "C" void kernel_launch(void* const* d_in, const int* in_sizes, int n_in,
                              void* d_out, int out_size) {
    // Resolve inputs by unique element counts, robust to metadata ordering.
    const float* targets = nullptr;   // B*K  = 8388608
    const float* bases   = nullptr;   // T*K  = 16777216
    const float* scaling = nullptr;   // K    = 1024
    const int*   indices = nullptr;   // B    = 8192
    long targets_n = 0, bases_n = 0;

    for (int j = 0; j < n_in; j++) {
        long n = in_sizes[j];
        if (n == K) {
            scaling = (const float*)d_in[j];
        } else if (n == 8192) {
            indices = (const int*)d_in[j];
        } else if (n == 8192L * K) {
            targets = (const float*)d_in[j];
            targets_n = n;
        } else {
            bases = (const float*)d_in[j];
            bases_n = n;
        }
    }
    if (!targets || !bases || !scaling || !indices) return;

    const int B = (int)(targets_n / K);   // 8192
    const int T = (int)(bases_n / K);     // 16384
    float* out = (float*)d_out;

    recompose_gemv_kernel<<<GRID, THREADS>>>(targets, bases, scaling, indices, B, T, out);
}